// round 9
// baseline (speedup 1.0000x reference)
#include <cuda_runtime.h>
#include <cuda_bf16.h>
#include <cstdint>

// smem byte layout
#define S_W1T  0          // 32KB: W1^T fp32 [n=64][k=128], 16B-slot XOR swizzle
#define S_X    32768      // 6 warps x 2 bufs x 16KB: X fp32 [32 rows][128 k] (h|t), swizzled
#define S_WGT  229376     // 6 warps x 32 floats
#define SMEM_BYTES 230144

#define N_UNITS 16384     // 4096 tiles * 4 factors
#define WARPS   6
#define THREADS (WARPS * 32)

static __device__ __forceinline__ uint32_t smem_u32(const void* p) {
    uint32_t a;
    asm("{ .reg .u64 t; cvta.to.shared.u64 t, %1; cvt.u32.u64 %0, t; }" : "=r"(a) : "l"(p));
    return a;
}
static __device__ __forceinline__ void cp_async16(uint32_t dst, const void* src) {
    asm volatile("cp.async.cg.shared.global [%0], [%1], 16;" :: "r"(dst), "l"(src) : "memory");
}

#define LDSM_X4(a0,a1,a2,a3,addr) \
    asm volatile("ldmatrix.sync.aligned.m8n8.x4.shared.b16 {%0,%1,%2,%3}, [%4];" \
        : "=r"(a0),"=r"(a1),"=r"(a2),"=r"(a3) : "r"(addr))
// D += A(tf32) @ B(tf32), m16n8k8, raw fp32 bits as tf32 (HW ignores low mantissa)
#define MMA_TF32(d,a0,a1,a2,a3,b0,b1) \
    asm volatile("mma.sync.aligned.m16n8k8.row.col.f32.tf32.tf32.f32 " \
        "{%0,%1,%2,%3}, {%4,%5,%6,%7}, {%8,%9}, {%0,%1,%2,%3};" \
        : "+f"((d)[0]),"+f"((d)[1]),"+f"((d)[2]),"+f"((d)[3]) \
        : "r"(a0),"r"(a1),"r"(a2),"r"(a3),"r"(b0),"r"(b1))

__global__ __launch_bounds__(THREADS, 1)
void kgat_tf32_kernel(const float* __restrict__ node_emb,
                      const float* __restrict__ W1,
                      const float* __restrict__ b1,
                      const float* __restrict__ W2,
                      const float* __restrict__ b2,
                      const int*   __restrict__ users,
                      const int*   __restrict__ items,
                      const int*   __restrict__ utri,
                      const int*   __restrict__ itri,
                      float*       __restrict__ out)
{
    extern __shared__ char smem[];
    const int tid  = threadIdx.x;
    const int wid  = tid >> 5;
    const int lane = tid & 31;
    const int g    = lane >> 2;     // 0..7
    const int tc   = lane & 3;      // 0..3

    // ---- one-time: W1^T fp32 smem [n][k], 16B-slot swizzle s' = (k>>2)^(n&7) ----
    {
        float* w1t = (float*)(smem + S_W1T);
        for (int i = tid; i < 8192; i += THREADS) {
            int kk = i >> 6, n = i & 63;              // W1[i] = W1[kk][n]
            w1t[n * 128 + ((((kk >> 2) ^ (n & 7)) << 2)) + (kk & 3)] = W1[i];
        }
    }
    __syncthreads();

    const uint32_t sb  = smem_u32(smem);
    const uint32_t Wu  = sb + S_W1T;
    const uint32_t Xu0 = sb + S_X + (uint32_t)wid * 32768u;
    float* swgt = (float*)(smem + S_WGT) + wid * 32;
    const float* node_f = node_emb;

    // ---- resident per-thread epilogue params ----
    float rb1[8][2], rw2[8][2];
    #pragma unroll
    for (int nt = 0; nt < 8; ++nt) {
        int n0 = nt * 8 + tc * 2;
        rb1[nt][0] = b1[n0];     rb1[nt][1] = b1[n0 + 1];
        rw2[nt][0] = W2[n0];     rw2[nt][1] = W2[n0 + 1];
    }
    const float b2v = b2[0];

    const int stride = gridDim.x * WARPS;
    const int u0 = blockIdx.x * WARPS + wid;

    // index loader for unit u (lane k's h/t node ids)
    auto load_idx = [&](int u, int& hi, int& ti) {
        const int tile  = u >> 2;
        const int tower = tile >> 11;
        const int b     = (tile >> 1) & 1023;
        const int layer = tile & 1;
        const int* tri  = tower ? itri : utri;
        hi = tri[((b * 3 + 0) * 2 + layer) * 32 + lane];
        ti = tri[((b * 3 + 2) * 2 + layer) * 32 + lane];
    };
    // gather burst for unit u into buffer at smem addr bufu
    auto issue_gather = [&](int u, uint32_t bufu, int hidx, int tidx) {
        const int f = u & 3;
        #pragma unroll
        for (int i = 0; i < 16; ++i) {
            const int r = 2 * i + (lane >> 4);
            const int c = lane & 15;
            const int hi = __shfl_sync(0xffffffffu, hidx, r);
            const int ti = __shfl_sync(0xffffffffu, tidx, r);
            const float* hsrc = node_f + (((size_t)hi * 4 + f) << 6) + (c << 2);
            const float* tsrc = node_f + (((size_t)ti * 4 + f) << 6) + (c << 2);
            cp_async16(bufu + (uint32_t)(r * 512) + (uint32_t)(((c        ) ^ (r & 7)) << 4), hsrc);
            cp_async16(bufu + (uint32_t)(r * 512) + (uint32_t)(((16 + c) ^ (r & 7)) << 4), tsrc);
        }
        asm volatile("cp.async.commit_group;" ::: "memory");
    };

    // ---- pipeline prologue ----
    int hidx_n = 0, tidx_n = 0;
    if (u0 < N_UNITS) {
        int hi, ti;
        load_idx(u0, hi, ti);
        issue_gather(u0, Xu0, hi, ti);
        if (u0 + stride < N_UNITS) load_idx(u0 + stride, hidx_n, tidx_n);
    }

    int cur = 0;
    for (int u = u0; u < N_UNITS; u += stride) {
        const int un = u + stride;
        const bool has_next = (un < N_UNITS);
        if (has_next) {
            issue_gather(un, Xu0 + (uint32_t)((cur ^ 1) << 14), hidx_n, tidx_n);
            const int unn = un + stride;
            if (unn < N_UNITS) load_idx(unn, hidx_n, tidx_n);
        }

        const int tile  = u >> 2;
        const int f     = u & 3;
        const int tower = tile >> 11;
        const int b     = (tile >> 1) & 1023;
        const int layer = tile & 1;

        // ---- origin slice (exact copy), overlaps the in-flight gathers ----
        if (layer == 0) {
            const int oidx = (tower ? items : users)[b];
            float* outp = out + ((size_t)(tower * 3) * 1024 + b) * 256 + f * 64;
            ((float2*)outp)[lane] =
                ((const float2*)(node_emb + ((size_t)oidx * 4 + f) * 64))[lane];
        }

        if (has_next) { asm volatile("cp.async.wait_group 1;" ::: "memory"); }
        else          { asm volatile("cp.async.wait_group 0;" ::: "memory"); }
        __syncwarp();

        const uint32_t Xu = Xu0 + (uint32_t)(cur << 14);
        const float*   Xf = (const float*)(smem + S_X + wid * 32768 + (cur << 14));

        // ---- GEMM: C[32][64] = X[32][128] @ W1[128][64], tf32 HMMA ----
        float acc[2][8][4];
        #pragma unroll
        for (int mt = 0; mt < 2; ++mt)
            #pragma unroll
            for (int nt = 0; nt < 8; ++nt)
                #pragma unroll
                for (int e = 0; e < 4; ++e) acc[mt][nt][e] = 0.f;

        #pragma unroll
        for (int kp = 0; kp < 8; ++kp) {          // ks = 2kp, 2kp+1
            uint32_t A[2][2][4];
            #pragma unroll
            for (int mt = 0; mt < 2; ++mt) {
                #pragma unroll
                for (int q = 0; q < 2; ++q) {
                    const int r  = mt * 16 + (lane & 15);
                    const int ch = 2 * (2 * kp + q) + (lane >> 4);
                    const uint32_t addr = Xu + (uint32_t)(r * 512) + (uint32_t)((ch ^ (r & 7)) << 4);
                    LDSM_X4(A[mt][q][0], A[mt][q][1], A[mt][q][2], A[mt][q][3], addr);
                }
            }
            #pragma unroll
            for (int nt = 0; nt < 8; ++nt) {
                uint32_t B[4];
                const int n  = nt * 8 + (lane & 7);
                const int ch = 4 * kp + (lane >> 3);
                const uint32_t baddr = Wu + (uint32_t)(n * 512) + (uint32_t)((ch ^ (n & 7)) << 4);
                LDSM_X4(B[0], B[1], B[2], B[3], baddr);
                MMA_TF32(acc[0][nt], A[0][0][0], A[0][0][1], A[0][0][2], A[0][0][3], B[0], B[1]);
                MMA_TF32(acc[1][nt], A[1][0][0], A[1][0][1], A[1][0][2], A[1][0][3], B[0], B[1]);
                MMA_TF32(acc[0][nt], A[0][1][0], A[0][1][1], A[0][1][2], A[0][1][3], B[2], B[3]);
                MMA_TF32(acc[1][nt], A[1][1][0], A[1][1][1], A[1][1][2], A[1][1][3], B[2], B[3]);
            }
        }

        // ---- logits: relu(C + b1) . W2 + b2 ----
        float lg[4];
        #pragma unroll
        for (int mt = 0; mt < 2; ++mt) {
            float p0 = 0.f, p1 = 0.f;
            #pragma unroll
            for (int nt = 0; nt < 8; ++nt) {
                p0 += fmaxf(acc[mt][nt][0] + rb1[nt][0], 0.f) * rw2[nt][0]
                    + fmaxf(acc[mt][nt][1] + rb1[nt][1], 0.f) * rw2[nt][1];
                p1 += fmaxf(acc[mt][nt][2] + rb1[nt][0], 0.f) * rw2[nt][0]
                    + fmaxf(acc[mt][nt][3] + rb1[nt][1], 0.f) * rw2[nt][1];
            }
            p0 += __shfl_xor_sync(0xffffffffu, p0, 1);
            p0 += __shfl_xor_sync(0xffffffffu, p0, 2);
            p1 += __shfl_xor_sync(0xffffffffu, p1, 1);
            p1 += __shfl_xor_sync(0xffffffffu, p1, 2);
            lg[mt * 2]     = p0 + b2v;   // row mt*16 + g
            lg[mt * 2 + 1] = p1 + b2v;   // row mt*16 + g + 8
        }

        // ---- softmax over the warp's 32 rows ----
        float m = fmaxf(fmaxf(lg[0], lg[1]), fmaxf(lg[2], lg[3]));
        #pragma unroll
        for (int o = 4; o <= 16; o <<= 1)
            m = fmaxf(m, __shfl_xor_sync(0xffffffffu, m, o));
        float e0 = __expf(lg[0] - m), e1 = __expf(lg[1] - m);
        float e2 = __expf(lg[2] - m), e3 = __expf(lg[3] - m);
        float s = e0 + e1 + e2 + e3;
        #pragma unroll
        for (int o = 4; o <= 16; o <<= 1)
            s += __shfl_xor_sync(0xffffffffu, s, o);
        const float rs = __frcp_rn(s);
        if (tc == 0) {
            swgt[g]      = e0 * rs;
            swgt[g + 8]  = e1 * rs;
            swgt[g + 16] = e2 * rs;
            swgt[g + 24] = e3 * rs;
        }
        __syncwarp();

        // ---- weighted sum of exact fp32 t (cols 64..127 of X) over k ----
        {
            const int ch0 = 16 + (lane >> 2);   // d0 = lane
            const int ch1 = 24 + (lane >> 2);   // d1 = lane + 32
            float a0 = 0.f, a1 = 0.f;
            #pragma unroll
            for (int rr = 0; rr < 32; ++rr) {
                const float w = swgt[rr];
                a0 += w * Xf[rr * 128 + ((ch0 ^ (rr & 7)) << 2) + (lane & 3)];
                a1 += w * Xf[rr * 128 + ((ch1 ^ (rr & 7)) << 2) + (lane & 3)];
            }
            float* outp = out + (((size_t)(tower * 3 + 1 + layer)) * 1024 + b) * 256 + f * 64;
            outp[lane]      = a0;
            outp[lane + 32] = a1;
        }
        __syncwarp();   // protect swgt / buffer before next iteration
        cur ^= 1;
    }
}

extern "C" void kernel_launch(void* const* d_in, const int* in_sizes, int n_in,
                              void* d_out, int out_size)
{
    const float* node_emb = (const float*)d_in[0];
    // d_in[1] = relation_emb: unused by the reference computation
    const float* W1    = (const float*)d_in[2];
    const float* b1    = (const float*)d_in[3];
    const float* W2    = (const float*)d_in[4];
    const float* b2    = (const float*)d_in[5];
    const int*   users = (const int*)d_in[6];
    const int*   items = (const int*)d_in[7];
    const int*   utri  = (const int*)d_in[8];
    const int*   itri  = (const int*)d_in[9];
    float*       out   = (float*)d_out;

    int nsm = 148;
    cudaDeviceGetAttribute(&nsm, cudaDevAttrMultiProcessorCount, 0);

    cudaFuncSetAttribute(kgat_tf32_kernel,
                         cudaFuncAttributeMaxDynamicSharedMemorySize, SMEM_BYTES);
    kgat_tf32_kernel<<<nsm, THREADS, SMEM_BYTES>>>(
        node_emb, W1, b1, W2, b2, users, items, utri, itri, out);
}